// round 1
// baseline (speedup 1.0000x reference)
#include <cuda_runtime.h>

// DWT3D: fused separable Haar 3D analysis + octant->channel repack.
// x: (B=2, N=128, N, N, C=4) f32, A: (128,128) Haar analysis matrix.
// out: (B, 64, 64, 64, 32) f32 where channel = octant*4 + c.
//
// Octant order (matching reference slicing, incl. its HLH==HHH duplication):
//   o0 = (iLo,jLo,kLo)  o1 = (iHi,jLo,kLo)  o2 = (iLo,jHi,kLo)  o3 = (iHi,jHi,kLo)
//   o4 = (iLo,jLo,kHi)  o5 = (iHi,jHi,kHi)  o6 = (iLo,jHi,kHi)  o7 = (iHi,jHi,kHi)

#define NN 128
#define CC 4
#define HALF 64

__device__ __forceinline__ float4 f4_comb(float s0, float4 a, float s1, float4 b) {
    float4 r;
    r.x = fmaf(s0, a.x, s1 * b.x);
    r.y = fmaf(s0, a.y, s1 * b.y);
    r.z = fmaf(s0, a.z, s1 * b.z);
    r.w = fmaf(s0, a.w, s1 * b.w);
    return r;
}

__global__ void __launch_bounds__(256) dwt3d_haar_kernel(
    const float* __restrict__ x,
    const float* __restrict__ A,
    float* __restrict__ out)
{
    int tid = blockIdx.x * blockDim.x + threadIdx.x;
    // total threads = B * 64^3 = 524288
    int d = tid & 63;
    int b = (tid >> 6) & 63;
    int a = (tid >> 12) & 63;
    int n = tid >> 18;

    // Haar coefficients from the actual A matrix (no wrap for L=2).
    const float h00 = __ldg(&A[0]);            // lowpass  tap 0
    const float h01 = __ldg(&A[1]);            // lowpass  tap 1
    const float h10 = __ldg(&A[HALF * NN]);    // highpass tap 0
    const float h11 = __ldg(&A[HALF * NN + 1]);// highpass tap 1

    // Load the 2x2x2 x C input block: 8 float4s, each (si,sj) pair is
    // 32 contiguous bytes (k fast, c fastest).
    const int i0 = 2 * a;
    const int j0 = 2 * b;
    const int k0 = 2 * d;
    const int base = ((n * NN + i0) * NN + j0) * NN * CC + k0 * CC;
    const int strideI = NN * NN * CC;   // +1 in i
    const int strideJ = NN * CC;        // +1 in j

    float4 v000, v001, v010, v011, v100, v101, v110, v111; // v[si][sj][sk]
    {
        const float4* p00 = (const float4*)(x + base);
        const float4* p01 = (const float4*)(x + base + strideJ);
        const float4* p10 = (const float4*)(x + base + strideI);
        const float4* p11 = (const float4*)(x + base + strideI + strideJ);
        v000 = p00[0]; v001 = p00[1];
        v010 = p01[0]; v011 = p01[1];
        v100 = p10[0]; v101 = p10[1];
        v110 = p11[0]; v111 = p11[1];
    }

    // Stage k: combine sk=0,1
    float4 kl00 = f4_comb(h00, v000, h01, v001);
    float4 kh00 = f4_comb(h10, v000, h11, v001);
    float4 kl01 = f4_comb(h00, v010, h01, v011);
    float4 kh01 = f4_comb(h10, v010, h11, v011);
    float4 kl10 = f4_comb(h00, v100, h01, v101);
    float4 kh10 = f4_comb(h10, v100, h11, v101);
    float4 kl11 = f4_comb(h00, v110, h01, v111);
    float4 kh11 = f4_comb(h10, v110, h11, v111);

    // Stage j: combine sj=0,1   (name: j{l,h}_{ktype}{si})
    float4 jl_l0 = f4_comb(h00, kl00, h01, kl01);
    float4 jh_l0 = f4_comb(h10, kl00, h11, kl01);
    float4 jl_h0 = f4_comb(h00, kh00, h01, kh01);
    float4 jh_h0 = f4_comb(h10, kh00, h11, kh01);
    float4 jl_l1 = f4_comb(h00, kl10, h01, kl11);
    float4 jh_l1 = f4_comb(h10, kl10, h11, kl11);
    float4 jl_h1 = f4_comb(h00, kh10, h01, kh11);
    float4 jh_h1 = f4_comb(h10, kh10, h11, kh11);

    // Stage i: combine si=0,1 -> 8 (iType,jType,kType) combos
    float4 lll = f4_comb(h00, jl_l0, h01, jl_l1);
    float4 hll = f4_comb(h10, jl_l0, h11, jl_l1);
    float4 lhl = f4_comb(h00, jh_l0, h01, jh_l1);
    float4 hhl = f4_comb(h10, jh_l0, h11, jh_l1);
    float4 llh = f4_comb(h00, jl_h0, h01, jl_h1);
    float4 hlh = f4_comb(h10, jl_h0, h11, jl_h1);
    float4 lhh = f4_comb(h00, jh_h0, h01, jh_h1);
    float4 hhh = f4_comb(h10, jh_h0, h11, jh_h1);
    (void)hlh; // reference never emits (iHi,jLo,kHi): its HLH slice duplicates HHH

    // Output: (n, a, b, d, 32) contiguous; octant order per reference slicing.
    float4* o = (float4*)(out + ((((n * HALF + a) * HALF + b) * HALF + d) << 5));
    o[0] = lll;  // LLL: (lo,lo,lo)
    o[1] = hll;  // LLH slice = y[:, hi, lo, lo]
    o[2] = lhl;  // LHL: (lo,hi,lo)
    o[3] = hhl;  // LHH: (hi,hi,lo)
    o[4] = llh;  // HLL slice = y[:, lo, lo, hi]
    o[5] = hhh;  // HLH slice = y[:, hi, hi, hi]  (reference duplication)
    o[6] = lhh;  // HHL slice = y[:, lo, hi, hi]
    o[7] = hhh;  // HHH: (hi,hi,hi)
}

extern "C" void kernel_launch(void* const* d_in, const int* in_sizes, int n_in,
                              void* d_out, int out_size) {
    const float* x = (const float*)d_in[0];
    const float* A = (const float*)d_in[1];
    float* out = (float*)d_out;
    // B*64^3 threads = 524288
    const int threads = 256;
    const int total = 2 * HALF * HALF * HALF;
    dwt3d_haar_kernel<<<total / threads, threads>>>(x, A, out);
}

// round 2
// speedup vs baseline: 1.1959x; 1.1959x over previous
#include <cuda_runtime.h>

// DWT3D: fused separable Haar 3D analysis + octant->channel repack.
// x: (B=2, N=128, N, N, C=4) f32, A: (128,128) Haar analysis matrix.
// out: (B, 64, 64, 64, 32) f32 where channel = octant*4 + c.
//
// Thread mapping: tid = voxel*4 + pair.  Pair p writes output float4s
// o[2p], o[2p+1] (32 contiguous bytes) -> warp stores 1024B contiguous.
//
// Octant/channel order (matching reference slicing, incl. HLH==HHH dup):
//   o0=lll o1=hll | o2=lhl o3=hhl | o4=llh o5=hhh | o6=lhh o7=hhh
//   pair0: ktype=L, jA=L, jB=L     pair1: ktype=L, jA=H, jB=H
//   pair2: ktype=H, jA=L, jB=H     pair3: ktype=H, jA=H, jB=H
//   out0 = i-lowpass(jA0,jA1), out1 = i-highpass(jB0,jB1)

#define NN 128
#define CC 4
#define HALF 64

__device__ __forceinline__ float4 f4_comb(float s0, float4 a, float s1, float4 b) {
    float4 r;
    r.x = fmaf(s0, a.x, s1 * b.x);
    r.y = fmaf(s0, a.y, s1 * b.y);
    r.z = fmaf(s0, a.z, s1 * b.z);
    r.w = fmaf(s0, a.w, s1 * b.w);
    return r;
}

__global__ void __launch_bounds__(256) dwt3d_haar_pair_kernel(
    const float* __restrict__ x,
    const float* __restrict__ A,
    float* __restrict__ out)
{
    const int tid = blockIdx.x * blockDim.x + threadIdx.x;
    const int pair = tid & 3;
    const int d = (tid >> 2) & 63;
    const int b = (tid >> 8) & 63;
    const int a = (tid >> 14) & 63;
    const int n = tid >> 20;

    // Haar coefficients from the actual A matrix (no wrap for L=2).
    const float h00 = __ldg(&A[0]);             // lowpass  tap 0
    const float h01 = __ldg(&A[1]);             // lowpass  tap 1
    const float h10 = __ldg(&A[HALF * NN]);     // highpass tap 0
    const float h11 = __ldg(&A[HALF * NN + 1]); // highpass tap 1

    // Per-pair filter selection (branchless).
    const bool kLo  = (pair < 2);            // k-stage type
    const bool jAlo = (pair == 0) | (pair == 2);
    const bool jBlo = (pair == 0);
    const float ck0  = kLo  ? h00 : h10, ck1  = kLo  ? h01 : h11;
    const float cja0 = jAlo ? h00 : h10, cja1 = jAlo ? h01 : h11;
    const float cjb0 = jBlo ? h00 : h10, cjb1 = jBlo ? h01 : h11;

    // Load the 2x2x2 x C input block for this voxel: 8 float4s.
    const int i0 = 2 * a;
    const int j0 = 2 * b;
    const int k0 = 2 * d;
    const int base = ((n * NN + i0) * NN + j0) * NN * CC + k0 * CC;
    const int strideI = NN * NN * CC;
    const int strideJ = NN * CC;

    const float4* p00 = (const float4*)(x + base);
    const float4* p01 = (const float4*)(x + base + strideJ);
    const float4* p10 = (const float4*)(x + base + strideI);
    const float4* p11 = (const float4*)(x + base + strideI + strideJ);
    float4 v000 = p00[0], v001 = p00[1];   // v[si][sj][sk]
    float4 v010 = p01[0], v011 = p01[1];
    float4 v100 = p10[0], v101 = p10[1];
    float4 v110 = p11[0], v111 = p11[1];

    // k-stage (this pair's ktype only): k[si][sj]
    float4 k00 = f4_comb(ck0, v000, ck1, v001);
    float4 k01 = f4_comb(ck0, v010, ck1, v011);
    float4 k10 = f4_comb(ck0, v100, ck1, v101);
    float4 k11 = f4_comb(ck0, v110, ck1, v111);

    // j-stage: two (possibly identical) j-filterings, per si
    float4 jA0 = f4_comb(cja0, k00, cja1, k01);
    float4 jA1 = f4_comb(cja0, k10, cja1, k11);
    float4 jB0 = f4_comb(cjb0, k00, cjb1, k01);
    float4 jB1 = f4_comb(cjb0, k10, cjb1, k11);

    // i-stage: out0 = lowpass of jA, out1 = highpass of jB
    float4 out0 = f4_comb(h00, jA0, h01, jA1);
    float4 out1 = f4_comb(h10, jB0, h11, jB1);

    // Store 32 contiguous bytes; warp covers 1024B contiguous.
    float4* o = (float4*)(out + ((((n * HALF + a) * HALF + b) * HALF + d) << 5));
    o[2 * pair]     = out0;
    o[2 * pair + 1] = out1;
}

extern "C" void kernel_launch(void* const* d_in, const int* in_sizes, int n_in,
                              void* d_out, int out_size) {
    const float* x = (const float*)d_in[0];
    const float* A = (const float*)d_in[1];
    float* out = (float*)d_out;
    const int threads = 256;
    const int total = 2 * HALF * HALF * HALF * 4;  // 4,194,304 threads
    dwt3d_haar_pair_kernel<<<total / threads, threads>>>(x, A, out);
}